// round 5
// baseline (speedup 1.0000x reference)
#include <cuda_runtime.h>
#include <cstdint>
#include <math.h>

// Problem sizes (fixed)
#define NE   32
#define HD   2048
#define ID   1536
#define NTOK 1024
#define TOPK 8
#define NP   (NTOK*TOPK)
#define BM   128
#define BK   32            // 32 fp32 k-values per chunk per row
#define MAXMT 96

// Staging: 384 rows x 160B (40 floats pitch), double buffered
#define PITCH  160
#define PITCHF 40
#define SROWS  384
#define STAGE  (SROWS*PITCH)     // 61440 B
#define SMEMB  (2*STAGE)         // 122880 B

// ---------------- device scratch ----------------
__device__ int   g_perm[NP];
__device__ float g_pw[NP];
__device__ int   g_off[NE+1];
__device__ int   g_mt_e[MAXMT];
__device__ int   g_mt_r[MAXMT];
__device__ int   g_nmt;
__device__ float g_act[(size_t)NP*ID];   // 48 MB

// ---------------- helpers ----------------
__device__ __forceinline__ uint32_t smem_u32(const void* p){
  uint32_t a;
  asm("{ .reg .u64 t; cvta.to.shared.u64 t, %1; cvt.u32.u64 %0, t; }" : "=r"(a) : "l"(p));
  return a;
}
__device__ __forceinline__ uint32_t tf32u(float x){
  uint32_t u; asm("cvt.rna.tf32.f32 %0, %1;" : "=r"(u) : "f"(x));
  return u;
}
__device__ __forceinline__ void sts64(uint32_t a, uint32_t x, uint32_t y){
  asm volatile("st.shared.v2.b32 [%0], {%1,%2};" :: "r"(a), "r"(x), "r"(y));
}
__device__ __forceinline__ float2 lds64(uint32_t a){
  float2 v; asm volatile("ld.shared.v2.f32 {%0,%1}, [%2];" : "=f"(v.x), "=f"(v.y) : "r"(a));
  return v;
}
__device__ __forceinline__ void mma_tf32(float d[4], const float a[4], const float2 b){
  asm volatile(
    "mma.sync.aligned.m16n8k8.row.col.f32.tf32.tf32.f32 "
    "{%0,%1,%2,%3}, {%4,%5,%6,%7}, {%8,%9}, {%0,%1,%2,%3};\n"
    : "+f"(d[0]), "+f"(d[1]), "+f"(d[2]), "+f"(d[3])
    : "r"(__float_as_uint(a[0])), "r"(__float_as_uint(a[1])),
      "r"(__float_as_uint(a[2])), "r"(__float_as_uint(a[3])),
      "r"(__float_as_uint(b.x)),  "r"(__float_as_uint(b.y)));
}
__device__ __forceinline__ void red2(float* p, float x, float y){
  asm volatile("red.global.add.v2.f32 [%0], {%1,%2};" :: "l"(p), "f"(x), "f"(y) : "memory");
}

// Store one 8-value k-group (f1 = k[8q..8q+3], f2 = k[8q+4..8q+7]) as 4
// interleaved (k, k+4) pairs with XOR-by-row swizzle. base = row*PITCH + q*32.
__device__ __forceinline__ void store_group(uint32_t base, int swz,
                                            const float4 f1, const float4 f2){
  sts64(base + ((0 ^ swz) << 3), tf32u(f1.x), tf32u(f2.x));
  sts64(base + ((1 ^ swz) << 3), tf32u(f1.y), tf32u(f2.y));
  sts64(base + ((2 ^ swz) << 3), tf32u(f1.z), tf32u(f2.z));
  sts64(base + ((3 ^ swz) << 3), tf32u(f1.w), tf32u(f2.w));
}

// ---------------- small kernels ----------------
__global__ void zero_out_kernel(float* __restrict__ out){
  int i = blockIdx.x*256 + threadIdx.x;
  if (i < NTOK*HD) out[i] = 0.f;
}

__global__ void route_kernel(const int* __restrict__ idx, const float* __restrict__ w){
  __shared__ int cnt[NE];
  __shared__ int cur[NE];
  __shared__ int soff[NE+1];
  int tid = threadIdx.x;
  if (tid < NE) cnt[tid] = 0;
  __syncthreads();
  for (int i = tid; i < NP; i += blockDim.x) atomicAdd(&cnt[idx[i]], 1);
  __syncthreads();
  if (tid == 0){
    int s = 0, nm = 0;
    for (int e = 0; e < NE; e++){
      soff[e] = s;
      for (int j = 0; j < cnt[e]; j += BM){ g_mt_e[nm] = e; g_mt_r[nm] = s + j; nm++; }
      s += cnt[e];
    }
    soff[NE] = s;
    g_nmt = nm;
  }
  __syncthreads();
  if (tid <= NE) g_off[tid] = soff[tid];
  if (tid <  NE) cur[tid]  = soff[tid];
  __syncthreads();
  for (int i = tid; i < NP; i += blockDim.x){
    int e = idx[i];
    int p = atomicAdd(&cur[e], 1);
    g_perm[p] = i / TOPK;
    g_pw[p]   = w[i];
  }
}

// =================== GEMM1 ===================
// Block: 128 tokens x 128 inter-channels (gate+up).
// Smem rows: [0,128) A tokens, [128,256) gate, [256,384) up.
#define G1_NKT (HD/BK)   // 64

__global__ __launch_bounds__(512,1) void gemm1_kernel(const float* __restrict__ X,
                                                      const float* __restrict__ GU)
{
  const int mt = blockIdx.x;
  if (mt >= g_nmt) return;
  const int e = g_mt_e[mt], row0 = g_mt_r[mt], pend = g_off[e+1];
  const int i0 = blockIdx.y * 128;

  extern __shared__ char smem[];
  const uint32_t sb = smem_u32(smem);

  const int t = threadIdx.x, lane = t & 31, wid = t >> 5;
  const int g = lane >> 2, c = lane & 3;
  const int mw = wid & 3, nw = wid >> 2;

  // ---- loader setup: 4 threads per row, 128 rows per pass, 3 passes ----
  const int lr = t >> 2, q = t & 3;
  const float* src[3];
  {
    int p = row0 + lr;
    int pc = (p < pend) ? p : row0;
    src[0] = X + (size_t)g_perm[pc]*HD + q*8;
    const float* gu_e = GU + (size_t)e*(2*ID)*HD;
    src[1] = gu_e + (size_t)(i0 + lr)*HD + q*8;
    src[2] = gu_e + (size_t)(ID + i0 + lr)*HD + q*8;
  }
  const int swz = (lr & 3);
  uint32_t sdst[3];
  sdst[0] = (uint32_t)lr*PITCH + (uint32_t)q*32;
  sdst[1] = sdst[0] + 128*PITCH;
  sdst[2] = sdst[0] + 256*PITCH;

  // ---- consumer fragment smem offsets ----
  const int csw = ((c ^ (g & 3)) << 3);
  uint32_t aoff[2][2], goff[4];
  #pragma unroll
  for (int mi = 0; mi < 2; mi++)
    #pragma unroll
    for (int h = 0; h < 2; h++)
      aoff[mi][h] = (uint32_t)(mw*32 + mi*16 + g + 8*h)*PITCH + csw;
  #pragma unroll
  for (int ni = 0; ni < 4; ni++)
    goff[ni] = (uint32_t)(128 + nw*32 + ni*8 + g)*PITCH + csw;

  float accg[2][4][4], accu[2][4][4];
  #pragma unroll
  for (int a=0;a<2;a++)
    #pragma unroll
    for (int b=0;b<4;b++)
      #pragma unroll
      for (int k=0;k<4;k++){ accg[a][b][k]=0.f; accu[a][b][k]=0.f; }

  float4 f[3][2];
  #pragma unroll
  for (int j = 0; j < 3; j++){
    f[j][0] = *(const float4*)(src[j]);
    f[j][1] = *(const float4*)(src[j] + 4);
  }
  #pragma unroll
  for (int j = 0; j < 3; j++) store_group(sb + sdst[j], swz, f[j][0], f[j][1]);

  for (int kt = 0; kt < G1_NKT; kt++){
    __syncthreads();
    const uint32_t sbuf = sb + (uint32_t)(kt & 1)*STAGE;
    if (kt + 1 < G1_NKT){
      const int ko = (kt + 1)*BK;
      #pragma unroll
      for (int j = 0; j < 3; j++){
        f[j][0] = *(const float4*)(src[j] + ko);
        f[j][1] = *(const float4*)(src[j] + ko + 4);
      }
    }
    #pragma unroll
    for (int ks = 0; ks < 4; ks++){
      const uint32_t kb = sbuf + ks*32;
      float2 p00 = lds64(kb + aoff[0][0]);
      float2 p01 = lds64(kb + aoff[0][1]);
      float2 p10 = lds64(kb + aoff[1][0]);
      float2 p11 = lds64(kb + aoff[1][1]);
      float a0[4] = { p00.x, p01.x, p00.y, p01.y };
      float a1[4] = { p10.x, p11.x, p10.y, p11.y };
      #pragma unroll
      for (int ni = 0; ni < 4; ni++){
        float2 bg = lds64(kb + goff[ni]);
        mma_tf32(accg[0][ni], a0, bg);
        mma_tf32(accg[1][ni], a1, bg);
        float2 bu = lds64(kb + goff[ni] + 128*PITCH);
        mma_tf32(accu[0][ni], a0, bu);
        mma_tf32(accu[1][ni], a1, bu);
      }
    }
    if (kt + 1 < G1_NKT){
      const uint32_t dbuf = sb + (uint32_t)((kt + 1) & 1)*STAGE;
      #pragma unroll
      for (int j = 0; j < 3; j++) store_group(dbuf + sdst[j], swz, f[j][0], f[j][1]);
    }
  }

  // epilogue: silu(gate)*up*router_weight -> g_act
  #pragma unroll
  for (int mi = 0; mi < 2; mi++){
    #pragma unroll
    for (int h = 0; h < 2; h++){
      int R = mw*32 + mi*16 + g + 8*h;
      int p = row0 + R;
      if (p < pend){
        float wgt = g_pw[p];
        float* arow = g_act + (size_t)p*ID + i0 + nw*32 + 2*c;
        #pragma unroll
        for (int ni = 0; ni < 4; ni++){
          float gv0 = accg[mi][ni][2*h],   uv0 = accu[mi][ni][2*h];
          float gv1 = accg[mi][ni][2*h+1], uv1 = accu[mi][ni][2*h+1];
          float o0 = wgt * (gv0 / (1.f + __expf(-gv0))) * uv0;
          float o1 = wgt * (gv1 / (1.f + __expf(-gv1))) * uv1;
          *(float2*)(arow + ni*8) = make_float2(o0, o1);
        }
      }
    }
  }
}

// =================== GEMM2 ===================
// Block: 128 act-rows x 256 h-channels. Smem rows: [0,128) A, [128,384) down.
#define G2_NKT (ID/BK)   // 48

__global__ __launch_bounds__(512,1) void gemm2_kernel(const float* __restrict__ DW,
                                                      float* __restrict__ out)
{
  const int mt = blockIdx.x;
  if (mt >= g_nmt) return;
  const int e = g_mt_e[mt], row0 = g_mt_r[mt], pend = g_off[e+1];
  const int h0 = blockIdx.y * 256;

  extern __shared__ char smem[];
  const uint32_t sb = smem_u32(smem);

  const int t = threadIdx.x, lane = t & 31, wid = t >> 5;
  const int g = lane >> 2, c = lane & 3;
  const int mw = wid & 3, nw = wid >> 2;

  const int lr = t >> 2, q = t & 3;
  const float* src[3];
  {
    int p = row0 + lr;
    int pc = (p < pend) ? p : row0;
    src[0] = g_act + (size_t)pc*ID + q*8;
    const float* dw_e = DW + (size_t)e*HD*ID;
    src[1] = dw_e + (size_t)(h0 + lr)*ID + q*8;
    src[2] = dw_e + (size_t)(h0 + 128 + lr)*ID + q*8;
  }
  const int swz = (lr & 3);
  uint32_t sdst[3];
  sdst[0] = (uint32_t)lr*PITCH + (uint32_t)q*32;
  sdst[1] = sdst[0] + 128*PITCH;
  sdst[2] = sdst[0] + 256*PITCH;

  const int csw = ((c ^ (g & 3)) << 3);
  uint32_t aoff[2][2], boff[8];
  #pragma unroll
  for (int mi = 0; mi < 2; mi++)
    #pragma unroll
    for (int h = 0; h < 2; h++)
      aoff[mi][h] = (uint32_t)(mw*32 + mi*16 + g + 8*h)*PITCH + csw;
  #pragma unroll
  for (int ni = 0; ni < 8; ni++)
    boff[ni] = (uint32_t)(128 + nw*64 + ni*8 + g)*PITCH + csw;

  float acc[2][8][4];
  #pragma unroll
  for (int a=0;a<2;a++)
    #pragma unroll
    for (int b=0;b<8;b++)
      #pragma unroll
      for (int k=0;k<4;k++) acc[a][b][k]=0.f;

  float4 f[3][2];
  #pragma unroll
  for (int j = 0; j < 3; j++){
    f[j][0] = *(const float4*)(src[j]);
    f[j][1] = *(const float4*)(src[j] + 4);
  }
  #pragma unroll
  for (int j = 0; j < 3; j++) store_group(sb + sdst[j], swz, f[j][0], f[j][1]);

  for (int kt = 0; kt < G2_NKT; kt++){
    __syncthreads();
    const uint32_t sbuf = sb + (uint32_t)(kt & 1)*STAGE;
    if (kt + 1 < G2_NKT){
      const int ko = (kt + 1)*BK;
      #pragma unroll
      for (int j = 0; j < 3; j++){
        f[j][0] = *(const float4*)(src[j] + ko);
        f[j][1] = *(const float4*)(src[j] + ko + 4);
      }
    }
    #pragma unroll
    for (int ks = 0; ks < 4; ks++){
      const uint32_t kb = sbuf + ks*32;
      float2 p00 = lds64(kb + aoff[0][0]);
      float2 p01 = lds64(kb + aoff[0][1]);
      float2 p10 = lds64(kb + aoff[1][0]);
      float2 p11 = lds64(kb + aoff[1][1]);
      float a0[4] = { p00.x, p01.x, p00.y, p01.y };
      float a1[4] = { p10.x, p11.x, p10.y, p11.y };
      #pragma unroll
      for (int ni = 0; ni < 8; ni++){
        float2 bb = lds64(kb + boff[ni]);
        mma_tf32(acc[0][ni], a0, bb);
        mma_tf32(acc[1][ni], a1, bb);
      }
    }
    if (kt + 1 < G2_NKT){
      const uint32_t dbuf = sb + (uint32_t)((kt + 1) & 1)*STAGE;
      #pragma unroll
      for (int j = 0; j < 3; j++) store_group(dbuf + sdst[j], swz, f[j][0], f[j][1]);
    }
  }

  // epilogue: vector scatter-add into out[token, h]
  #pragma unroll
  for (int mi = 0; mi < 2; mi++){
    #pragma unroll
    for (int h = 0; h < 2; h++){
      int R = mw*32 + mi*16 + g + 8*h;
      int p = row0 + R;
      if (p < pend){
        int tok = g_perm[p];
        float* orow = out + (size_t)tok*HD + h0 + nw*64 + 2*c;
        #pragma unroll
        for (int ni = 0; ni < 8; ni++){
          red2(orow + ni*8, acc[mi][ni][2*h], acc[mi][ni][2*h+1]);
        }
      }
    }
  }
}

// ---------------- launch ----------------
extern "C" void kernel_launch(void* const* d_in, const int* in_sizes, int n_in,
                              void* d_out, int out_size)
{
  const float* X  = (const float*)d_in[0];
  const int*   ix = (const int*)d_in[1];
  const float* tw = (const float*)d_in[2];
  const float* GU = (const float*)d_in[3];
  const float* DW = (const float*)d_in[4];
  float* out = (float*)d_out;
  (void)in_sizes; (void)n_in; (void)out_size;

  cudaFuncSetAttribute(gemm1_kernel, cudaFuncAttributeMaxDynamicSharedMemorySize, SMEMB);
  cudaFuncSetAttribute(gemm2_kernel, cudaFuncAttributeMaxDynamicSharedMemorySize, SMEMB);

  zero_out_kernel<<<(NTOK*HD + 255)/256, 256>>>(out);
  route_kernel<<<1, 256>>>(ix, tw);
  gemm1_kernel<<<dim3(MAXMT, ID/128), 512, SMEMB>>>(X, GU);
  gemm2_kernel<<<dim3(MAXMT, HD/256), 512, SMEMB>>>(DW, out);
}

// round 6
// speedup vs baseline: 1.6281x; 1.6281x over previous
#include <cuda_runtime.h>
#include <cuda_fp16.h>
#include <cstdint>
#include <math.h>

// Problem sizes (fixed)
#define NE   32
#define HD   2048
#define ID   1536
#define NTOK 1024
#define TOPK 8
#define NP   (NTOK*TOPK)
#define BM   128
#define MAXMT 96

// ---------------- device scratch ----------------
__device__ int    g_perm[NP];
__device__ float  g_pw[NP];
__device__ int    g_off[NE+1];
__device__ int    g_mt_e[MAXMT];
__device__ int    g_mt_r[MAXMT];
__device__ int    g_nmt;
__device__ __half g_act[(size_t)NP*ID];   // 24 MB fp16 activations

// ---------------- helpers ----------------
__device__ __forceinline__ uint32_t smem_u32(const void* p){
  uint32_t a;
  asm("{ .reg .u64 t; cvta.to.shared.u64 t, %1; cvt.u32.u64 %0, t; }" : "=r"(a) : "l"(p));
  return a;
}
// pack 2 fp32 -> f16x2 (lo in low half)
__device__ __forceinline__ uint32_t f22h(float lo, float hi){
  uint32_t r; asm("cvt.rn.f16x2.f32 %0, %1, %2;" : "=r"(r) : "f"(hi), "f"(lo));
  return r;
}
__device__ __forceinline__ void ldsm4(uint32_t* r, uint32_t a){
  asm volatile("ldmatrix.sync.aligned.m8n8.x4.shared.b16 {%0,%1,%2,%3}, [%4];"
    : "=r"(r[0]),"=r"(r[1]),"=r"(r[2]),"=r"(r[3]) : "r"(a));
}
__device__ __forceinline__ void sts128(uint32_t a, uint4 v){
  asm volatile("st.shared.v4.b32 [%0], {%1,%2,%3,%4};"
    :: "r"(a), "r"(v.x), "r"(v.y), "r"(v.z), "r"(v.w));
}
__device__ __forceinline__ void mma16816(float* d, const uint32_t* a, const uint32_t* b){
  asm volatile(
    "mma.sync.aligned.m16n8k16.row.col.f32.f16.f16.f32 "
    "{%0,%1,%2,%3},{%4,%5,%6,%7},{%8,%9},{%0,%1,%2,%3};"
    : "+f"(d[0]),"+f"(d[1]),"+f"(d[2]),"+f"(d[3])
    : "r"(a[0]),"r"(a[1]),"r"(a[2]),"r"(a[3]), "r"(b[0]),"r"(b[1]));
}
__device__ __forceinline__ void red2(float* p, float x, float y){
  asm volatile("red.global.add.v2.f32 [%0], {%1,%2};" :: "l"(p), "f"(x), "f"(y) : "memory");
}
// row -> swizzled byte offset (64B pitch); bits[4:5] then XOR'd with c<<4
__device__ __forceinline__ uint32_t swz(uint32_t r){
  return (r << 6) ^ (((r >> 1) & 3u) << 4);
}
// load 8 fp32 -> 16B of fp16
__device__ __forceinline__ uint4 ld8cvt(const float* s){
  float4 u = *(const float4*)s; float4 v = *(const float4*)(s+4);
  uint4 r; r.x = f22h(u.x,u.y); r.y = f22h(u.z,u.w);
  r.z = f22h(v.x,v.y); r.w = f22h(v.z,v.w);
  return r;
}

// ---------------- small kernels ----------------
__global__ void zero_out_kernel(float* __restrict__ out){
  int i = blockIdx.x*256 + threadIdx.x;
  if (i < NTOK*HD) out[i] = 0.f;
}

__global__ void route_kernel(const int* __restrict__ idx, const float* __restrict__ w){
  __shared__ int cnt[NE];
  __shared__ int cur[NE];
  __shared__ int soff[NE+1];
  int tid = threadIdx.x;
  if (tid < NE) cnt[tid] = 0;
  __syncthreads();
  for (int i = tid; i < NP; i += blockDim.x) atomicAdd(&cnt[idx[i]], 1);
  __syncthreads();
  if (tid == 0){
    int s = 0, nm = 0;
    for (int e = 0; e < NE; e++){
      soff[e] = s;
      for (int j = 0; j < cnt[e]; j += BM){ g_mt_e[nm] = e; g_mt_r[nm] = s + j; nm++; }
      s += cnt[e];
    }
    soff[NE] = s;
    g_nmt = nm;
  }
  __syncthreads();
  if (tid <= NE) g_off[tid] = soff[tid];
  if (tid <  NE) cur[tid]  = soff[tid];
  __syncthreads();
  for (int i = tid; i < NP; i += blockDim.x){
    int e = idx[i];
    int p = atomicAdd(&cur[e], 1);
    g_perm[p] = i / TOPK;
    g_pw[p]   = w[i];
  }
}

// =================== GEMM1 ===================
// Block 128 tokens x 128 channels (gate+up). Smem rows: [0,128) A,
// [128,256) gate, [256,384) up. 64B/row, double buffered = 48KB.
#define G1_STAGE 24576
#define G1_SMEM  49152
#define G1_NKT   (HD/32)   // 64

__global__ __launch_bounds__(512,1) void gemm1_kernel(const float* __restrict__ X,
                                                      const float* __restrict__ GU)
{
  const int mt = blockIdx.x;
  if (mt >= g_nmt) return;
  const int e = g_mt_e[mt], row0 = g_mt_r[mt], pend = g_off[e+1];
  const int i0 = blockIdx.y * 128;

  extern __shared__ char smem[];
  const uint32_t sb = smem_u32(smem);
  const int t = threadIdx.x, lane = t & 31, wid = t >> 5;
  const int mw = wid & 3, nw = wid >> 2;       // 4m x 4n warps

  // ---- producer: 4 threads/row, 128 rows/pass, 3 passes (A, gate, up) ----
  const int lr = t >> 2, q = t & 3;
  int pa = row0 + lr; int pc = (pa < pend) ? pa : row0;
  const float* srcA = X + (size_t)g_perm[pc]*HD + q*8;
  const float* gu_e = GU + (size_t)e*(2*ID)*HD;
  const float* srcG = gu_e + (size_t)(i0 + lr)*HD + q*8;
  const float* srcU = gu_e + (size_t)(ID + i0 + lr)*HD + q*8;
  const uint32_t sA = swz(lr) ^ (q << 4);
  const uint32_t sG = sA + 8192, sU = sA + 16384;

  // ---- consumer fragment base offsets ----
  const int ca = lane >> 4;
  const uint32_t pa0 = swz(mw*32 + (lane & 15)) ^ (ca << 4);
  const uint32_t pa1 = swz(mw*32 + 16 + (lane & 15)) ^ (ca << 4);
  const int brl = (lane & 7) + (((lane >> 4) & 1) << 3);
  const int cb = (lane >> 3) & 1;
  const uint32_t pg0 = swz(128 + nw*32 + brl) ^ (cb << 4);
  const uint32_t pg1 = swz(128 + nw*32 + 16 + brl) ^ (cb << 4);
  const uint32_t pu0 = pg0 + 8192;
  const uint32_t pu1 = pg1 + 8192;

  float accg[2][4][4] = {}, accu[2][4][4] = {};

  // preload k-chunk 0
  sts128(sb + sA, ld8cvt(srcA));
  sts128(sb + sG, ld8cvt(srcG));
  sts128(sb + sU, ld8cvt(srcU));
  __syncthreads();

  for (int kt = 0; kt < G1_NKT; kt++){
    const uint32_t sbuf = sb + (uint32_t)(kt & 1)*G1_STAGE;
    uint4 fA, fG, fU;
    if (kt + 1 < G1_NKT){
      const int ko = (kt + 1)*32;
      fA = ld8cvt(srcA + ko); fG = ld8cvt(srcG + ko); fU = ld8cvt(srcU + ko);
    }
    #pragma unroll
    for (int ks = 0; ks < 2; ks++){
      const uint32_t k5 = (uint32_t)ks << 5;
      uint32_t A0[4], A1[4], Bg[8], Bu[8];
      ldsm4(A0,   sbuf + (pa0 ^ k5));
      ldsm4(A1,   sbuf + (pa1 ^ k5));
      ldsm4(Bg,   sbuf + (pg0 ^ k5));
      ldsm4(Bg+4, sbuf + (pg1 ^ k5));
      ldsm4(Bu,   sbuf + (pu0 ^ k5));
      ldsm4(Bu+4, sbuf + (pu1 ^ k5));
      #pragma unroll
      for (int ni = 0; ni < 4; ni++){
        mma16816(accg[0][ni], A0, Bg + ni*2);
        mma16816(accg[1][ni], A1, Bg + ni*2);
        mma16816(accu[0][ni], A0, Bu + ni*2);
        mma16816(accu[1][ni], A1, Bu + ni*2);
      }
    }
    if (kt + 1 < G1_NKT){
      const uint32_t dbuf = sb + (uint32_t)((kt + 1) & 1)*G1_STAGE;
      sts128(dbuf + sA, fA); sts128(dbuf + sG, fG); sts128(dbuf + sU, fU);
      __syncthreads();
    }
  }

  // ---- epilogue: silu(gate)*up*router_weight -> g_act (fp16) ----
  const int g = lane >> 2, c = lane & 3;
  #pragma unroll
  for (int mi = 0; mi < 2; mi++){
    #pragma unroll
    for (int h = 0; h < 2; h++){
      int R = mw*32 + mi*16 + g + 8*h;
      int p = row0 + R;
      if (p < pend){
        float wgt = g_pw[p];
        __half* arow = g_act + (size_t)p*ID + i0 + nw*32 + 2*c;
        #pragma unroll
        for (int ni = 0; ni < 4; ni++){
          float gv0 = accg[mi][ni][2*h],   gv1 = accg[mi][ni][2*h+1];
          float uv0 = accu[mi][ni][2*h],   uv1 = accu[mi][ni][2*h+1];
          float o0 = wgt * (gv0 / (1.f + __expf(-gv0))) * uv0;
          float o1 = wgt * (gv1 / (1.f + __expf(-gv1))) * uv1;
          *(__half2*)(arow + ni*8) = __floats2half2_rn(o0, o1);
        }
      }
    }
  }
}

// =================== GEMM2 ===================
// Block 128 act-rows x 128 h-channels. Smem rows: [0,128) A(fp16 src),
// [128,256) down. 32KB double-buffered, 256 threads, 2 CTAs/SM.
#define G2_STAGE 16384
#define G2_SMEM  32768
#define G2_NKT   (ID/32)   // 48

__global__ __launch_bounds__(256,2) void gemm2_kernel(const float* __restrict__ DW,
                                                      float* __restrict__ out)
{
  const int mt = blockIdx.x;
  if (mt >= g_nmt) return;
  const int e = g_mt_e[mt], row0 = g_mt_r[mt], pend = g_off[e+1];
  const int h0 = blockIdx.y * 128;

  extern __shared__ char smem[];
  const uint32_t sb = smem_u32(smem);
  const int t = threadIdx.x, lane = t & 31, wid = t >> 5;
  const int mw = wid & 3, nw = wid >> 2;       // 4m x 2n warps (32m x 64n each)

  // ---- producer: 4 threads/row; A 128 rows (2 passes), B 128 rows (2 passes)
  const int lr = t >> 2, q = t & 3;
  const __half* srcA[2];
  const float*  srcB[2];
  uint32_t sAo[2], sBo[2];
  const float* dw_e = DW + (size_t)e*HD*ID;
  #pragma unroll
  for (int j = 0; j < 2; j++){
    int r = lr + j*64;
    int p = row0 + r; int pc = (p < pend) ? p : row0;
    srcA[j] = g_act + (size_t)pc*ID + q*8;
    srcB[j] = dw_e + (size_t)(h0 + r)*ID + q*8;
    sAo[j] = swz(r) ^ (q << 4);
    sBo[j] = sAo[j] + 8192;
  }

  // ---- consumer fragment offsets ----
  const int ca = lane >> 4;
  const uint32_t pa0 = swz(mw*32 + (lane & 15)) ^ (ca << 4);
  const uint32_t pa1 = swz(mw*32 + 16 + (lane & 15)) ^ (ca << 4);
  const int brl = (lane & 7) + (((lane >> 4) & 1) << 3);
  const int cb = (lane >> 3) & 1;
  uint32_t pb[4];
  #pragma unroll
  for (int j = 0; j < 4; j++)
    pb[j] = swz(128 + nw*64 + j*16 + brl) ^ (cb << 4);

  float acc[2][8][4] = {};

  // preload
  sts128(sb + sAo[0], *(const uint4*)srcA[0]);
  sts128(sb + sAo[1], *(const uint4*)srcA[1]);
  sts128(sb + sBo[0], ld8cvt(srcB[0]));
  sts128(sb + sBo[1], ld8cvt(srcB[1]));
  __syncthreads();

  for (int kt = 0; kt < G2_NKT; kt++){
    const uint32_t sbuf = sb + (uint32_t)(kt & 1)*G2_STAGE;
    uint4 fA0, fA1, fB0, fB1;
    if (kt + 1 < G2_NKT){
      const int ko = (kt + 1)*32;     // 32 elements per chunk
      fA0 = *(const uint4*)(srcA[0] + ko);
      fA1 = *(const uint4*)(srcA[1] + ko);
      fB0 = ld8cvt(srcB[0] + ko);
      fB1 = ld8cvt(srcB[1] + ko);
    }
    #pragma unroll
    for (int ks = 0; ks < 2; ks++){
      const uint32_t k5 = (uint32_t)ks << 5;
      uint32_t A0[4], A1[4], B[16];
      ldsm4(A0, sbuf + (pa0 ^ k5));
      ldsm4(A1, sbuf + (pa1 ^ k5));
      #pragma unroll
      for (int j = 0; j < 4; j++) ldsm4(B + j*4, sbuf + (pb[j] ^ k5));
      #pragma unroll
      for (int ni = 0; ni < 8; ni++){
        mma16816(acc[0][ni], A0, B + ni*2);
        mma16816(acc[1][ni], A1, B + ni*2);
      }
    }
    if (kt + 1 < G2_NKT){
      const uint32_t dbuf = sb + (uint32_t)((kt + 1) & 1)*G2_STAGE;
      sts128(dbuf + sAo[0], fA0); sts128(dbuf + sAo[1], fA1);
      sts128(dbuf + sBo[0], fB0); sts128(dbuf + sBo[1], fB1);
      __syncthreads();
    }
  }

  // ---- epilogue: vector scatter-add into out[token, h] ----
  const int g = lane >> 2, c = lane & 3;
  #pragma unroll
  for (int mi = 0; mi < 2; mi++){
    #pragma unroll
    for (int h = 0; h < 2; h++){
      int R = mw*32 + mi*16 + g + 8*h;
      int p = row0 + R;
      if (p < pend){
        int tok = g_perm[p];
        float* orow = out + (size_t)tok*HD + h0 + nw*64 + 2*c;
        #pragma unroll
        for (int ni = 0; ni < 8; ni++){
          red2(orow + ni*8, acc[mi][ni][2*h], acc[mi][ni][2*h+1]);
        }
      }
    }
  }
}

// ---------------- launch ----------------
extern "C" void kernel_launch(void* const* d_in, const int* in_sizes, int n_in,
                              void* d_out, int out_size)
{
  const float* X  = (const float*)d_in[0];
  const int*   ix = (const int*)d_in[1];
  const float* tw = (const float*)d_in[2];
  const float* GU = (const float*)d_in[3];
  const float* DW = (const float*)d_in[4];
  float* out = (float*)d_out;
  (void)in_sizes; (void)n_in; (void)out_size;

  cudaFuncSetAttribute(gemm1_kernel, cudaFuncAttributeMaxDynamicSharedMemorySize, G1_SMEM);
  cudaFuncSetAttribute(gemm2_kernel, cudaFuncAttributeMaxDynamicSharedMemorySize, G2_SMEM);

  zero_out_kernel<<<(NTOK*HD + 255)/256, 256>>>(out);
  route_kernel<<<1, 256>>>(ix, tw);
  gemm1_kernel<<<dim3(MAXMT, ID/128), 512, G1_SMEM>>>(X, GU);
  gemm2_kernel<<<dim3(MAXMT, HD/128), 256, G2_SMEM>>>(DW, out);
}